// round 1
// baseline (speedup 1.0000x reference)
#include <cuda_runtime.h>
#include <cuda_bf16.h>
#include <math.h>

// ---------------- problem constants ----------------
#define NMAX      50000
#define EMAX      800000
#define CH        128
#define NGRAPHS   64
#define BN_EPS    1e-5f

// ---------------- scratch (device globals; no allocation allowed) ----------------
__device__ float g_hw[NMAX * CH];     // GEMM output, rows pre-scaled by dinv
__device__ float g_actA[NMAX * CH];   // ping
__device__ float g_actB[NMAX * CH];   // pong
__device__ float g_dinv[NMAX];
__device__ int   g_indeg[NMAX];
__device__ int   g_rowstart[NMAX + 1];
__device__ int   g_fill[NMAX];
__device__ int   g_edges[EMAX];
__device__ float g_bnsum[2 * CH];     // [0:128) sum, [128:256) sumsq
__device__ float g_bnscale[CH];
__device__ float g_bnshift[CH];
__device__ float g_pool[NGRAPHS * CH + NGRAPHS]; // sums then counts
__device__ float g_y1[NGRAPHS * CH];
__device__ float g_y2[NGRAPHS * CH];

// ---------------- helpers ----------------
__device__ __forceinline__ float gelu_exact(float x) {
    return 0.5f * x * (1.0f + erff(x * 0.70710678118654752440f));
}

// packed f32x2 FMA: d = {a,a}*{bx,by} + {cx,cy}
__device__ __forceinline__ float2 ffma2(float a, float2 b, float2 c) {
    float2 d;
    asm("{\n\t"
        ".reg .b64 A, B, C, D;\n\t"
        "mov.b64 A, {%2, %2};\n\t"
        "mov.b64 B, {%3, %4};\n\t"
        "mov.b64 C, {%5, %6};\n\t"
        "fma.rn.f32x2 D, A, B, C;\n\t"
        "mov.b64 {%0, %1}, D;\n\t"
        "}"
        : "=f"(d.x), "=f"(d.y)
        : "f"(a), "f"(b.x), "f"(b.y), "f"(c.x), "f"(c.y));
    return d;
}

// ---------------- small utility kernels ----------------
__global__ void k_zero_f(float* p, int n) {
    int i = blockIdx.x * blockDim.x + threadIdx.x;
    int st = gridDim.x * blockDim.x;
    for (; i < n; i += st) p[i] = 0.0f;
}
__global__ void k_zero_i(int* p, int n) {
    int i = blockIdx.x * blockDim.x + threadIdx.x;
    int st = gridDim.x * blockDim.x;
    for (; i < n; i += st) p[i] = 0;
}

// ---------------- degree / CSR build ----------------
__global__ void k_count(const int* __restrict__ dst, int* __restrict__ indeg, int E) {
    int i = blockIdx.x * blockDim.x + threadIdx.x;
    if (i < E) atomicAdd(&indeg[dst[i]], 1);
}

__global__ void k_dinv(const int* __restrict__ indeg, float* __restrict__ dinv, int N) {
    int i = blockIdx.x * blockDim.x + threadIdx.x;
    if (i < N) dinv[i] = rsqrtf((float)(indeg[i] + 1)); // +1 = self loop
}

// single-block exclusive scan of indeg -> rowstart (+ copy into fill)
__global__ void k_scan(const int* __restrict__ indeg, int* __restrict__ rowstart,
                       int* __restrict__ fill, int N) {
    __shared__ int wsum[32];
    int tid = threadIdx.x, lane = tid & 31, wid = tid >> 5;
    int running = 0;
    for (int base = 0; base < N; base += 1024) {
        int idx = base + tid;
        int v = (idx < N) ? indeg[idx] : 0;
        int x = v;
        #pragma unroll
        for (int off = 1; off < 32; off <<= 1) {
            int y = __shfl_up_sync(0xffffffffu, x, off);
            if (lane >= off) x += y;
        }
        if (lane == 31) wsum[wid] = x;
        __syncthreads();
        if (wid == 0) {
            int w = wsum[lane];
            #pragma unroll
            for (int off = 1; off < 32; off <<= 1) {
                int y = __shfl_up_sync(0xffffffffu, w, off);
                if (lane >= off) w += y;
            }
            wsum[lane] = w;
        }
        __syncthreads();
        int warpOff = (wid > 0) ? wsum[wid - 1] : 0;
        int excl = x - v + warpOff + running;
        if (idx < N) { rowstart[idx] = excl; fill[idx] = excl; }
        running += wsum[31];
        __syncthreads();
    }
    if (tid == 0) rowstart[N] = running;
}

__global__ void k_fillcsr(const int* __restrict__ src, const int* __restrict__ dst,
                          int* __restrict__ fill, int* __restrict__ edges, int E) {
    int i = blockIdx.x * blockDim.x + threadIdx.x;
    if (i < E) {
        int pos = atomicAdd(&fill[dst[i]], 1);
        edges[pos] = src[i];
    }
}

// ---------------- GEMM: out[r] = dinv[r] * (A[r] @ W), 128x128 weights ----------------
// block tile 128x128, BK=32, 256 threads, 8x8 microtile with packed f32x2
#define BM 128
#define BNT 128
#define BK 32
#define APAD 4

__global__ void __launch_bounds__(256, 2)
k_gemm(const float* __restrict__ A, const float* __restrict__ W,
       const float* __restrict__ dinv, float* __restrict__ out, int N) {
    __shared__ float shA[BK][BM + APAD]; // [k][m] (transposed)
    __shared__ float shB[BK][BNT];       // [k][n]

    int tid = threadIdx.x;
    int tx = tid & 15, ty = tid >> 4;
    int m0 = ty * 8, n0 = tx * 8;
    int rowBase = blockIdx.x * BM;

    float2 acc[8][4];
    #pragma unroll
    for (int r = 0; r < 8; r++)
        #pragma unroll
        for (int c = 0; c < 4; c++) acc[r][c] = make_float2(0.f, 0.f);

    for (int kt = 0; kt < CH; kt += BK) {
        // load A tile (transposed into shared)
        #pragma unroll
        for (int i = 0; i < 4; i++) {
            int p = tid + i * 256;      // 0..1023 float4 slots (128 rows x 8)
            int r = p >> 3;
            int c4 = p & 7;
            int grow = rowBase + r;
            float4 v = make_float4(0.f, 0.f, 0.f, 0.f);
            if (grow < N) v = *(const float4*)&A[grow * CH + kt + c4 * 4];
            shA[c4 * 4 + 0][r] = v.x;
            shA[c4 * 4 + 1][r] = v.y;
            shA[c4 * 4 + 2][r] = v.z;
            shA[c4 * 4 + 3][r] = v.w;
        }
        // load W tile
        #pragma unroll
        for (int i = 0; i < 4; i++) {
            int p = tid + i * 256;      // 0..1023 float4 slots (32 k x 32)
            int r = p >> 5;
            int c4 = p & 31;
            *(float4*)&shB[r][c4 * 4] = *(const float4*)&W[(kt + r) * CH + c4 * 4];
        }
        __syncthreads();

        #pragma unroll
        for (int k = 0; k < BK; k++) {
            float a[8];
            float2 b[4];
            *(float4*)&a[0] = *(const float4*)&shA[k][m0];
            *(float4*)&a[4] = *(const float4*)&shA[k][m0 + 4];
            *(float4*)&b[0] = *(const float4*)&shB[k][n0];
            *(float4*)&b[2] = *(const float4*)&shB[k][n0 + 4];
            #pragma unroll
            for (int r = 0; r < 8; r++) {
                #pragma unroll
                for (int c = 0; c < 4; c++)
                    acc[r][c] = ffma2(a[r], b[c], acc[r][c]);
            }
        }
        __syncthreads();
    }

    #pragma unroll
    for (int r = 0; r < 8; r++) {
        int grow = rowBase + m0 + r;
        if (grow < N) {
            float s = dinv[grow];
            float4 o;
            o.x = acc[r][0].x * s; o.y = acc[r][0].y * s;
            o.z = acc[r][1].x * s; o.w = acc[r][1].y * s;
            *(float4*)&out[grow * CH + n0] = o;
            o.x = acc[r][2].x * s; o.y = acc[r][2].y * s;
            o.z = acc[r][3].x * s; o.w = acc[r][3].y * s;
            *(float4*)&out[grow * CH + n0 + 4] = o;
        }
    }
}

// ---------------- aggregation: out[i] = dinv[i]*(hws[i] + sum_in hws[src]) + bias ----------------
__global__ void k_agg(const float* __restrict__ hws, const int* __restrict__ edges,
                      const int* __restrict__ rowstart, const float* __restrict__ dinv,
                      const float* __restrict__ bias, float* __restrict__ out, int N) {
    int warp = (blockIdx.x * blockDim.x + threadIdx.x) >> 5;
    int lane = threadIdx.x & 31;
    if (warp >= N) return;
    const float4* base = (const float4*)hws;
    float4 acc = base[warp * 32 + lane];   // self-loop term (already dinv-scaled)
    int s = rowstart[warp], e = rowstart[warp + 1];
    int i = s;
    for (; i + 1 < e; i += 2) {
        int s0 = __ldg(&edges[i]);
        int s1 = __ldg(&edges[i + 1]);
        float4 v0 = base[s0 * 32 + lane];
        float4 v1 = base[s1 * 32 + lane];
        acc.x += v0.x + v1.x; acc.y += v0.y + v1.y;
        acc.z += v0.z + v1.z; acc.w += v0.w + v1.w;
    }
    if (i < e) {
        int s0 = __ldg(&edges[i]);
        float4 v0 = base[s0 * 32 + lane];
        acc.x += v0.x; acc.y += v0.y; acc.z += v0.z; acc.w += v0.w;
    }
    float d = dinv[warp];
    float4 bb = ((const float4*)bias)[lane];
    float4 o;
    o.x = acc.x * d + bb.x; o.y = acc.y * d + bb.y;
    o.z = acc.z * d + bb.z; o.w = acc.w * d + bb.w;
    ((float4*)out)[warp * 32 + lane] = o;
}

// ---------------- batch norm ----------------
__global__ void k_bnstats(const float* __restrict__ h, float* __restrict__ sums, int N) {
    int col = threadIdx.x; // 128 threads
    float s = 0.f, s2 = 0.f;
    for (int r = blockIdx.x; r < N; r += gridDim.x) {
        float v = h[r * CH + col];
        s += v; s2 += v * v;
    }
    atomicAdd(&sums[col], s);
    atomicAdd(&sums[CH + col], s2);
}

__global__ void k_bnfinal(const float* __restrict__ sums, const float* __restrict__ g,
                          const float* __restrict__ beta, float* __restrict__ scale,
                          float* __restrict__ shift, float Nf) {
    int c = threadIdx.x;
    float mean = sums[c] / Nf;
    float var = sums[CH + c] / Nf - mean * mean;
    float s = g[c] * rsqrtf(var + BN_EPS);
    scale[c] = s;
    shift[c] = beta[c] - mean * s;
}

__global__ void k_bn_gelu(float* __restrict__ h, const float* __restrict__ scale,
                          const float* __restrict__ shift, int n4) {
    int i = blockIdx.x * blockDim.x + threadIdx.x;
    int st = gridDim.x * blockDim.x;
    const float4* s4 = (const float4*)scale;
    const float4* f4 = (const float4*)shift;
    float4* h4 = (float4*)h;
    for (; i < n4; i += st) {
        int c = i & 31;
        float4 v = h4[i];
        float4 sc = s4[c], sf = f4[c];
        v.x = gelu_exact(v.x * sc.x + sf.x);
        v.y = gelu_exact(v.y * sc.y + sf.y);
        v.z = gelu_exact(v.z * sc.z + sf.z);
        v.w = gelu_exact(v.w * sc.w + sf.w);
        h4[i] = v;
    }
}

// ---------------- pooling ----------------
__global__ void k_pool(const float* __restrict__ h, const int* __restrict__ batch,
                       float* __restrict__ psum, float* __restrict__ pcnt, int N) {
    __shared__ float sh[NGRAPHS * CH];
    __shared__ float shc[NGRAPHS];
    int tid = threadIdx.x; // 256
    for (int i = tid; i < NGRAPHS * CH; i += 256) sh[i] = 0.f;
    if (tid < NGRAPHS) shc[tid] = 0.f;
    __syncthreads();
    int rpb = (N + gridDim.x - 1) / gridDim.x;
    int r0 = blockIdx.x * rpb;
    int r1 = min(r0 + rpb, N);
    int col = tid & 127;
    for (int r = r0 + (tid >> 7); r < r1; r += 2) {
        int g = batch[r];
        atomicAdd(&sh[g * CH + col], h[r * CH + col]);
        if (col == 0) atomicAdd(&shc[g], 1.0f);
    }
    __syncthreads();
    for (int i = tid; i < NGRAPHS * CH; i += 256)
        if (sh[i] != 0.f) atomicAdd(&psum[i], sh[i]);
    if (tid < NGRAPHS && shc[tid] != 0.f) atomicAdd(&pcnt[tid], shc[tid]);
}

// ---------------- head ----------------
__global__ void k_head1(const float* __restrict__ psum, const float* __restrict__ pcnt,
                        const float* __restrict__ W, const float* __restrict__ b,
                        float* __restrict__ y) {
    __shared__ float row[CH];
    int g = blockIdx.x, t = threadIdx.x;
    float cnt = fmaxf(pcnt[g], 1.0f);
    row[t] = psum[g * CH + t] / cnt;
    __syncthreads();
    float acc = b[t];
    #pragma unroll 8
    for (int k = 0; k < CH; k++) acc += row[k] * W[k * CH + t];
    y[g * CH + t] = gelu_exact(acc);
}

__global__ void k_head2(const float* __restrict__ x, const float* __restrict__ W,
                        const float* __restrict__ b, float* __restrict__ y) {
    __shared__ float row[CH];
    int g = blockIdx.x, t = threadIdx.x;
    row[t] = x[g * CH + t];
    __syncthreads();
    float acc = b[t];
    #pragma unroll 8
    for (int k = 0; k < CH; k++) acc += row[k] * W[k * CH + t];
    y[g * CH + t] = gelu_exact(acc);
}

__global__ void k_head3(const float* __restrict__ x, const float* __restrict__ W,
                        const float* __restrict__ b, float* __restrict__ out) {
    __shared__ float row[CH];
    int g = blockIdx.x, t = threadIdx.x;
    row[t] = x[g * CH + t];
    __syncthreads();
    if (t < 10) {
        float acc = b[t];
        #pragma unroll 8
        for (int k = 0; k < CH; k++) acc += row[k] * W[k * 10 + t];
        out[g * 10 + t] = acc;
    }
}

// ---------------- driver ----------------
static float* devptr_f(const void* sym) { void* p = nullptr; cudaGetSymbolAddress(&p, sym); return (float*)p; }

extern "C" void kernel_launch(void* const* d_in, const int* in_sizes, int n_in,
                              void* d_out, int out_size) {
    const float* x      = (const float*)d_in[0];
    const int*   eidx   = (const int*)d_in[1];
    const int*   batch  = (const int*)d_in[2];
    const float* Wb0 = (const float*)d_in[4];
    const float* bb0 = (const float*)d_in[5];
    const float* gb0 = (const float*)d_in[6];
    const float* betab0 = (const float*)d_in[7];
    const float* Wb1 = (const float*)d_in[8];
    const float* bb1 = (const float*)d_in[9];
    const float* Wa0 = (const float*)d_in[10];
    const float* ba0 = (const float*)d_in[11];
    const float* ga0 = (const float*)d_in[12];
    const float* bea0 = (const float*)d_in[13];
    const float* Wa1 = (const float*)d_in[14];
    const float* ba1 = (const float*)d_in[15];
    const float* ga1 = (const float*)d_in[16];
    const float* bea1 = (const float*)d_in[17];
    const float* Wa2 = (const float*)d_in[18];
    const float* ba2 = (const float*)d_in[19];
    const float* Wh0 = (const float*)d_in[20];
    const float* bh0 = (const float*)d_in[21];
    const float* Wh1 = (const float*)d_in[22];
    const float* bh1 = (const float*)d_in[23];
    const float* Wh2 = (const float*)d_in[24];
    const float* bh2 = (const float*)d_in[25];

    int N = in_sizes[0] / CH;     // 50000
    int E = in_sizes[1] / 2;      // 800000
    const int* esrc = eidx;
    const int* edst = eidx + E;

    // resolve device-global scratch
    float* hw    = devptr_f(g_hw);
    float* actA  = devptr_f(g_actA);
    float* actB  = devptr_f(g_actB);
    float* dinv  = devptr_f(g_dinv);
    float* bnsum = devptr_f(g_bnsum);
    float* bnsc  = devptr_f(g_bnscale);
    float* bnsh  = devptr_f(g_bnshift);
    float* pool  = devptr_f(g_pool);
    float* y1    = devptr_f(g_y1);
    float* y2    = devptr_f(g_y2);
    int *indeg, *rowstart, *fill, *edges;
    { void* p; cudaGetSymbolAddress(&p, g_indeg);    indeg = (int*)p; }
    { void* p; cudaGetSymbolAddress(&p, g_rowstart); rowstart = (int*)p; }
    { void* p; cudaGetSymbolAddress(&p, g_fill);     fill = (int*)p; }
    { void* p; cudaGetSymbolAddress(&p, g_edges);    edges = (int*)p; }

    int gemmGrid = (N + BM - 1) / BM;
    int aggGrid  = (N + 7) / 8;     // 8 warps / block
    int n4 = N * (CH / 4);

    // ---- CSR + degree prep ----
    k_zero_i<<<64, 256>>>(indeg, N);
    k_count<<<(E + 255) / 256, 256>>>(edst, indeg, E);
    k_dinv<<<(N + 255) / 256, 256>>>(indeg, dinv, N);
    k_scan<<<1, 1024>>>(indeg, rowstart, fill, N);
    k_fillcsr<<<(E + 255) / 256, 256>>>(esrc, edst, fill, edges, E);

    // ---- Layer 0: conv(x, Wb0, bb0) -> BN(gb0,betab0) -> gelu (in actA) ----
    k_gemm<<<gemmGrid, 256>>>(x, Wb0, dinv, hw, N);
    k_agg<<<aggGrid, 256>>>(hw, edges, rowstart, dinv, bb0, actA, N);
    k_zero_f<<<1, 256>>>(bnsum, 2 * CH);
    k_bnstats<<<512, CH>>>(actA, bnsum, N);
    k_bnfinal<<<1, CH>>>(bnsum, gb0, betab0, bnsc, bnsh, (float)N);
    k_bn_gelu<<<2048, 256>>>(actA, bnsc, bnsh, n4);

    // ---- Layer 1: conv(actA, Wb1, bb1) -> actB (no BN) ----
    k_gemm<<<gemmGrid, 256>>>(actA, Wb1, dinv, hw, N);
    k_agg<<<aggGrid, 256>>>(hw, edges, rowstart, dinv, bb1, actB, N);

    // ---- Layer 2: conv(actB, Wa0, ba0) -> BN(ga0,bea0) -> gelu (in actA) ----
    k_gemm<<<gemmGrid, 256>>>(actB, Wa0, dinv, hw, N);
    k_agg<<<aggGrid, 256>>>(hw, edges, rowstart, dinv, ba0, actA, N);
    k_zero_f<<<1, 256>>>(bnsum, 2 * CH);
    k_bnstats<<<512, CH>>>(actA, bnsum, N);
    k_bnfinal<<<1, CH>>>(bnsum, ga0, bea0, bnsc, bnsh, (float)N);
    k_bn_gelu<<<2048, 256>>>(actA, bnsc, bnsh, n4);

    // ---- Layer 3: conv(actA, Wa1, ba1) -> BN(ga1,bea1) -> gelu (in actB) ----
    k_gemm<<<gemmGrid, 256>>>(actA, Wa1, dinv, hw, N);
    k_agg<<<aggGrid, 256>>>(hw, edges, rowstart, dinv, ba1, actB, N);
    k_zero_f<<<1, 256>>>(bnsum, 2 * CH);
    k_bnstats<<<512, CH>>>(actB, bnsum, N);
    k_bnfinal<<<1, CH>>>(bnsum, ga1, bea1, bnsc, bnsh, (float)N);
    k_bn_gelu<<<2048, 256>>>(actB, bnsc, bnsh, n4);

    // ---- Layer 4: conv(actB, Wa2, ba2) -> actA (no activation) ----
    k_gemm<<<gemmGrid, 256>>>(actB, Wa2, dinv, hw, N);
    k_agg<<<aggGrid, 256>>>(hw, edges, rowstart, dinv, ba2, actA, N);

    // ---- global mean pool ----
    k_zero_f<<<33, 256>>>(pool, NGRAPHS * CH + NGRAPHS);
    k_pool<<<64, 256>>>(actA, batch, pool, pool + NGRAPHS * CH, N);

    // ---- MLP head ----
    k_head1<<<NGRAPHS, CH>>>(pool, pool + NGRAPHS * CH, Wh0, bh0, y1);
    k_head2<<<NGRAPHS, CH>>>(y1, Wh1, bh1, y2);
    k_head3<<<NGRAPHS, CH>>>(y2, Wh2, bh2, (float*)d_out);
}

// round 2
// speedup vs baseline: 1.1213x; 1.1213x over previous
#include <cuda_runtime.h>
#include <cuda_bf16.h>
#include <math.h>

// ---------------- problem constants ----------------
#define NMAX      50000
#define EMAX      800000
#define CH        128
#define NGRAPHS   64
#define BN_EPS    1e-5f

// ---------------- scratch (device globals; no allocation allowed) ----------------
__device__ float g_hw[NMAX * CH];     // GEMM output, rows pre-scaled by dinv
__device__ float g_actA[NMAX * CH];   // ping
__device__ float g_actB[NMAX * CH];   // pong
__device__ float g_dinv[NMAX];
__device__ int   g_indeg[NMAX];
__device__ int   g_rowstart[NMAX + 1];
__device__ int   g_fill[NMAX];
__device__ int   g_edges[EMAX];
__device__ int   g_blocksum[64];
__device__ int   g_blockoff[64];
__device__ float g_bnsum[3 * 2 * CH];   // 3 BN layers x (sum[128], sumsq[128])
__device__ float g_bnscale[3 * CH];
__device__ float g_bnshift[3 * CH];
__device__ float g_pool[NGRAPHS * CH + NGRAPHS]; // sums then counts
__device__ float g_y1[NGRAPHS * CH];
__device__ float g_y2[NGRAPHS * CH];

// ---------------- helpers ----------------
__device__ __forceinline__ float gelu_exact(float x) {
    return 0.5f * x * (1.0f + erff(x * 0.70710678118654752440f));
}

// packed f32x2 FMA: d = {a,a}*{bx,by} + {cx,cy}
__device__ __forceinline__ float2 ffma2(float a, float2 b, float2 c) {
    float2 d;
    asm("{\n\t"
        ".reg .b64 A, B, C, D;\n\t"
        "mov.b64 A, {%2, %2};\n\t"
        "mov.b64 B, {%3, %4};\n\t"
        "mov.b64 C, {%5, %6};\n\t"
        "fma.rn.f32x2 D, A, B, C;\n\t"
        "mov.b64 {%0, %1}, D;\n\t"
        "}"
        : "=f"(d.x), "=f"(d.y)
        : "f"(a), "f"(b.x), "f"(b.y), "f"(c.x), "f"(c.y));
    return d;
}

// ---------------- init: zero indeg + bn sums + pool buffers ----------------
__global__ void k_init(int* __restrict__ indeg, float* __restrict__ bnsum,
                       float* __restrict__ pool, int N) {
    int i = blockIdx.x * blockDim.x + threadIdx.x;
    int st = gridDim.x * blockDim.x;
    for (int j = i; j < N; j += st) indeg[j] = 0;
    for (int j = i; j < 3 * 2 * CH; j += st) bnsum[j] = 0.f;
    for (int j = i; j < NGRAPHS * CH + NGRAPHS; j += st) pool[j] = 0.f;
}

// ---------------- degree / CSR build ----------------
__global__ void k_count(const int* __restrict__ dst, int* __restrict__ indeg, int E) {
    int i = blockIdx.x * blockDim.x + threadIdx.x;
    if (i < E) atomicAdd(&indeg[dst[i]], 1);
}

// per-block exclusive scan of 1024 elems; also computes dinv
__global__ void k_scan_blk(const int* __restrict__ indeg, int* __restrict__ scanned,
                           int* __restrict__ blocksum, float* __restrict__ dinv, int N) {
    __shared__ int wsum[32];
    int tid = threadIdx.x, lane = tid & 31, wid = tid >> 5;
    int idx = blockIdx.x * 1024 + tid;
    int v = (idx < N) ? indeg[idx] : 0;
    if (idx < N) dinv[idx] = rsqrtf((float)(v + 1));  // +1 = self loop
    int x = v;
    #pragma unroll
    for (int off = 1; off < 32; off <<= 1) {
        int y = __shfl_up_sync(0xffffffffu, x, off);
        if (lane >= off) x += y;
    }
    if (lane == 31) wsum[wid] = x;
    __syncthreads();
    if (wid == 0) {
        int w = wsum[lane];
        #pragma unroll
        for (int off = 1; off < 32; off <<= 1) {
            int y = __shfl_up_sync(0xffffffffu, w, off);
            if (lane >= off) w += y;
        }
        wsum[lane] = w;
    }
    __syncthreads();
    int excl = x - v + (wid ? wsum[wid - 1] : 0);
    if (idx < N) scanned[idx] = excl;
    if (tid == 1023) blocksum[blockIdx.x] = excl + v;  // block total
}

// single-warp scan of block sums (B <= 64)
__global__ void k_scan_top(const int* __restrict__ blocksum, int* __restrict__ blockoff,
                           int* __restrict__ rowstart, int B, int N) {
    int lane = threadIdx.x;  // 32 threads
    int run = 0;
    for (int base = 0; base < B; base += 32) {
        int v = (base + lane < B) ? blocksum[base + lane] : 0;
        int x = v;
        #pragma unroll
        for (int off = 1; off < 32; off <<= 1) {
            int y = __shfl_up_sync(0xffffffffu, x, off);
            if (lane >= off) x += y;
        }
        if (base + lane < B) blockoff[base + lane] = x - v + run;
        run += __shfl_sync(0xffffffffu, x, 31);
    }
    if (lane == 0) rowstart[N] = run;
}

__global__ void k_scan_add(int* __restrict__ rowstart, const int* __restrict__ blockoff,
                           int* __restrict__ fill, int N) {
    int idx = blockIdx.x * blockDim.x + threadIdx.x;
    if (idx < N) {
        int v = rowstart[idx] + blockoff[idx >> 10];
        rowstart[idx] = v;
        fill[idx] = v;
    }
}

__global__ void k_fillcsr(const int* __restrict__ src, const int* __restrict__ dst,
                          int* __restrict__ fill, int* __restrict__ edges, int E) {
    int i = blockIdx.x * blockDim.x + threadIdx.x;
    if (i < E) {
        int pos = atomicAdd(&fill[dst[i]], 1);
        edges[pos] = src[i];
    }
}

// ---------------- GEMM: out[r] = dinv[r] * (A[r] @ W), 128x128 weights ----------------
#define BM 128
#define BNT 128
#define BK 32
#define APAD 4

__global__ void __launch_bounds__(256, 2)
k_gemm(const float* __restrict__ A, const float* __restrict__ W,
       const float* __restrict__ dinv, float* __restrict__ out, int N) {
    __shared__ float shA[BK][BM + APAD]; // [k][m] (transposed)
    __shared__ float shB[BK][BNT];       // [k][n]

    int tid = threadIdx.x;
    int tx = tid & 15, ty = tid >> 4;
    int m0 = ty * 8, n0 = tx * 8;
    int rowBase = blockIdx.x * BM;

    float2 acc[8][4];
    #pragma unroll
    for (int r = 0; r < 8; r++)
        #pragma unroll
        for (int c = 0; c < 4; c++) acc[r][c] = make_float2(0.f, 0.f);

    for (int kt = 0; kt < CH; kt += BK) {
        #pragma unroll
        for (int i = 0; i < 4; i++) {
            int p = tid + i * 256;
            int r = p >> 3;
            int c4 = p & 7;
            int grow = rowBase + r;
            float4 v = make_float4(0.f, 0.f, 0.f, 0.f);
            if (grow < N) v = *(const float4*)&A[grow * CH + kt + c4 * 4];
            shA[c4 * 4 + 0][r] = v.x;
            shA[c4 * 4 + 1][r] = v.y;
            shA[c4 * 4 + 2][r] = v.z;
            shA[c4 * 4 + 3][r] = v.w;
        }
        #pragma unroll
        for (int i = 0; i < 4; i++) {
            int p = tid + i * 256;
            int r = p >> 5;
            int c4 = p & 31;
            *(float4*)&shB[r][c4 * 4] = *(const float4*)&W[(kt + r) * CH + c4 * 4];
        }
        __syncthreads();

        #pragma unroll
        for (int k = 0; k < BK; k++) {
            float a[8];
            float2 b[4];
            *(float4*)&a[0] = *(const float4*)&shA[k][m0];
            *(float4*)&a[4] = *(const float4*)&shA[k][m0 + 4];
            *(float4*)&b[0] = *(const float4*)&shB[k][n0];
            *(float4*)&b[2] = *(const float4*)&shB[k][n0 + 4];
            #pragma unroll
            for (int r = 0; r < 8; r++) {
                #pragma unroll
                for (int c = 0; c < 4; c++)
                    acc[r][c] = ffma2(a[r], b[c], acc[r][c]);
            }
        }
        __syncthreads();
    }

    #pragma unroll
    for (int r = 0; r < 8; r++) {
        int grow = rowBase + m0 + r;
        if (grow < N) {
            float s = dinv[grow];
            float4 o;
            o.x = acc[r][0].x * s; o.y = acc[r][0].y * s;
            o.z = acc[r][1].x * s; o.w = acc[r][1].y * s;
            *(float4*)&out[grow * CH + n0] = o;
            o.x = acc[r][2].x * s; o.y = acc[r][2].y * s;
            o.z = acc[r][3].x * s; o.w = acc[r][3].y * s;
            *(float4*)&out[grow * CH + n0 + 4] = o;
        }
    }
}

// ---------------- aggregation + optional fused BN stats ----------------
// out[i] = dinv[i]*(hws[i] + sum_in hws[src]) + bias; stats: column sum/sumsq
__global__ void k_agg(const float* __restrict__ hws, const int* __restrict__ edges,
                      const int* __restrict__ rowstart, const float* __restrict__ dinv,
                      const float* __restrict__ bias, float* __restrict__ out,
                      float* __restrict__ stats, int N) {
    __shared__ float sh[8][CH];
    int wId = threadIdx.x >> 5;
    int lane = threadIdx.x & 31;
    int node = blockIdx.x * 8 + wId;
    bool valid = node < N;

    const float4* base = (const float4*)hws;
    float4 acc = make_float4(0.f, 0.f, 0.f, 0.f);
    int s = 0, e = 0;
    float d = 0.f;
    if (valid) {
        acc = base[node * 32 + lane];   // self-loop term (pre-scaled by dinv[src])
        s = rowstart[node]; e = rowstart[node + 1];
        d = dinv[node];
    }
    int i = s;
    for (; i + 3 < e; i += 4) {
        int s0 = __ldg(&edges[i]);
        int s1 = __ldg(&edges[i + 1]);
        int s2 = __ldg(&edges[i + 2]);
        int s3 = __ldg(&edges[i + 3]);
        float4 v0 = base[s0 * 32 + lane];
        float4 v1 = base[s1 * 32 + lane];
        float4 v2 = base[s2 * 32 + lane];
        float4 v3 = base[s3 * 32 + lane];
        acc.x += (v0.x + v1.x) + (v2.x + v3.x);
        acc.y += (v0.y + v1.y) + (v2.y + v3.y);
        acc.z += (v0.z + v1.z) + (v2.z + v3.z);
        acc.w += (v0.w + v1.w) + (v2.w + v3.w);
    }
    for (; i < e; i++) {
        int s0 = __ldg(&edges[i]);
        float4 v0 = base[s0 * 32 + lane];
        acc.x += v0.x; acc.y += v0.y; acc.z += v0.z; acc.w += v0.w;
    }
    float4 o = make_float4(0.f, 0.f, 0.f, 0.f);
    if (valid) {
        float4 bb = ((const float4*)bias)[lane];
        o.x = acc.x * d + bb.x; o.y = acc.y * d + bb.y;
        o.z = acc.z * d + bb.z; o.w = acc.w * d + bb.w;
        ((float4*)out)[node * 32 + lane] = o;
    }

    if (stats) {
        *(float4*)&sh[wId][lane * 4] = o;  // zeros for invalid nodes
        __syncthreads();
        int t = threadIdx.x;
        int c = t & 127;
        bool sq = t >= 128;
        float a2 = 0.f;
        #pragma unroll
        for (int w = 0; w < 8; w++) {
            float v = sh[w][c];
            a2 += sq ? v * v : v;
        }
        atomicAdd(&stats[sq ? CH + c : c], a2);
    }
}

// ---------------- batch norm finalize ----------------
__global__ void k_bnfinal(const float* __restrict__ sums, const float* __restrict__ g,
                          const float* __restrict__ beta, float* __restrict__ scale,
                          float* __restrict__ shift, float Nf) {
    int c = threadIdx.x;
    float mean = sums[c] / Nf;
    float var = sums[CH + c] / Nf - mean * mean;
    float s = g[c] * rsqrtf(var + BN_EPS);
    scale[c] = s;
    shift[c] = beta[c] - mean * s;
}

__global__ void k_bn_gelu(float* __restrict__ h, const float* __restrict__ scale,
                          const float* __restrict__ shift, int n4) {
    int i = blockIdx.x * blockDim.x + threadIdx.x;
    int st = gridDim.x * blockDim.x;
    const float4* s4 = (const float4*)scale;
    const float4* f4 = (const float4*)shift;
    float4* h4 = (float4*)h;
    for (; i < n4; i += st) {
        int c = i & 31;
        float4 v = h4[i];
        float4 sc = s4[c], sf = f4[c];
        v.x = gelu_exact(v.x * sc.x + sf.x);
        v.y = gelu_exact(v.y * sc.y + sf.y);
        v.z = gelu_exact(v.z * sc.z + sf.z);
        v.w = gelu_exact(v.w * sc.w + sf.w);
        h4[i] = v;
    }
}

// ---------------- pooling ----------------
__global__ void k_pool(const float* __restrict__ h, const int* __restrict__ batch,
                       float* __restrict__ psum, float* __restrict__ pcnt, int N) {
    __shared__ float sh[NGRAPHS * CH];
    __shared__ float shc[NGRAPHS];
    int tid = threadIdx.x; // 256
    for (int i = tid; i < NGRAPHS * CH; i += 256) sh[i] = 0.f;
    if (tid < NGRAPHS) shc[tid] = 0.f;
    __syncthreads();
    int rpb = (N + gridDim.x - 1) / gridDim.x;
    int r0 = blockIdx.x * rpb;
    int r1 = min(r0 + rpb, N);
    int col = tid & 127;
    for (int r = r0 + (tid >> 7); r < r1; r += 2) {
        int g = batch[r];
        atomicAdd(&sh[g * CH + col], h[r * CH + col]);
        if (col == 0) atomicAdd(&shc[g], 1.0f);
    }
    __syncthreads();
    for (int i = tid; i < NGRAPHS * CH; i += 256)
        if (sh[i] != 0.f) atomicAdd(&psum[i], sh[i]);
    if (tid < NGRAPHS && shc[tid] != 0.f) atomicAdd(&pcnt[tid], shc[tid]);
}

// ---------------- head ----------------
__global__ void k_head1(const float* __restrict__ psum, const float* __restrict__ pcnt,
                        const float* __restrict__ W, const float* __restrict__ b,
                        float* __restrict__ y) {
    __shared__ float row[CH];
    int g = blockIdx.x, t = threadIdx.x;
    float cnt = fmaxf(pcnt[g], 1.0f);
    row[t] = psum[g * CH + t] / cnt;
    __syncthreads();
    float acc = b[t];
    #pragma unroll 8
    for (int k = 0; k < CH; k++) acc += row[k] * W[k * CH + t];
    y[g * CH + t] = gelu_exact(acc);
}

__global__ void k_head2(const float* __restrict__ x, const float* __restrict__ W,
                        const float* __restrict__ b, float* __restrict__ y) {
    __shared__ float row[CH];
    int g = blockIdx.x, t = threadIdx.x;
    row[t] = x[g * CH + t];
    __syncthreads();
    float acc = b[t];
    #pragma unroll 8
    for (int k = 0; k < CH; k++) acc += row[k] * W[k * CH + t];
    y[g * CH + t] = gelu_exact(acc);
}

__global__ void k_head3(const float* __restrict__ x, const float* __restrict__ W,
                        const float* __restrict__ b, float* __restrict__ out) {
    __shared__ float row[CH];
    int g = blockIdx.x, t = threadIdx.x;
    row[t] = x[g * CH + t];
    __syncthreads();
    if (t < 10) {
        float acc = b[t];
        #pragma unroll 8
        for (int k = 0; k < CH; k++) acc += row[k] * W[k * 10 + t];
        out[g * 10 + t] = acc;
    }
}

// ---------------- driver ----------------
static float* devptr_f(const void* sym) { void* p = nullptr; cudaGetSymbolAddress(&p, sym); return (float*)p; }
static int* devptr_i(const void* sym) { void* p = nullptr; cudaGetSymbolAddress(&p, sym); return (int*)p; }

extern "C" void kernel_launch(void* const* d_in, const int* in_sizes, int n_in,
                              void* d_out, int out_size) {
    const float* x      = (const float*)d_in[0];
    const int*   eidx   = (const int*)d_in[1];
    const int*   batch  = (const int*)d_in[2];
    const float* Wb0 = (const float*)d_in[4];
    const float* bb0 = (const float*)d_in[5];
    const float* gb0 = (const float*)d_in[6];
    const float* betab0 = (const float*)d_in[7];
    const float* Wb1 = (const float*)d_in[8];
    const float* bb1 = (const float*)d_in[9];
    const float* Wa0 = (const float*)d_in[10];
    const float* ba0 = (const float*)d_in[11];
    const float* ga0 = (const float*)d_in[12];
    const float* bea0 = (const float*)d_in[13];
    const float* Wa1 = (const float*)d_in[14];
    const float* ba1 = (const float*)d_in[15];
    const float* ga1 = (const float*)d_in[16];
    const float* bea1 = (const float*)d_in[17];
    const float* Wa2 = (const float*)d_in[18];
    const float* ba2 = (const float*)d_in[19];
    const float* Wh0 = (const float*)d_in[20];
    const float* bh0 = (const float*)d_in[21];
    const float* Wh1 = (const float*)d_in[22];
    const float* bh1 = (const float*)d_in[23];
    const float* Wh2 = (const float*)d_in[24];
    const float* bh2 = (const float*)d_in[25];

    int N = in_sizes[0] / CH;     // 50000
    int E = in_sizes[1] / 2;      // 800000
    const int* esrc = eidx;
    const int* edst = eidx + E;

    float* hw    = devptr_f(g_hw);
    float* actA  = devptr_f(g_actA);
    float* actB  = devptr_f(g_actB);
    float* dinv  = devptr_f(g_dinv);
    float* bnsum = devptr_f(g_bnsum);
    float* bnsc  = devptr_f(g_bnscale);
    float* bnsh  = devptr_f(g_bnshift);
    float* pool  = devptr_f(g_pool);
    float* y1    = devptr_f(g_y1);
    float* y2    = devptr_f(g_y2);
    int* indeg    = devptr_i(g_indeg);
    int* rowstart = devptr_i(g_rowstart);
    int* fill     = devptr_i(g_fill);
    int* edges    = devptr_i(g_edges);
    int* blocksum = devptr_i(g_blocksum);
    int* blockoff = devptr_i(g_blockoff);

    int gemmGrid = (N + BM - 1) / BM;
    int aggGrid  = (N + 7) / 8;     // 8 warps / block, 1 node per warp
    int n4 = N * (CH / 4);
    int scanB = (N + 1023) / 1024;

    // ---- CSR + degree prep ----
    k_init<<<128, 256>>>(indeg, bnsum, pool, N);
    k_count<<<(E + 255) / 256, 256>>>(edst, indeg, E);
    k_scan_blk<<<scanB, 1024>>>(indeg, rowstart, blocksum, dinv, N);
    k_scan_top<<<1, 32>>>(blocksum, blockoff, rowstart, scanB, N);
    k_scan_add<<<(N + 255) / 256, 256>>>(rowstart, blockoff, fill, N);
    k_fillcsr<<<(E + 255) / 256, 256>>>(esrc, edst, fill, edges, E);

    // ---- Layer 0: conv(x, Wb0, bb0) -> BN0 -> gelu (in actA) ----
    k_gemm<<<gemmGrid, 256>>>(x, Wb0, dinv, hw, N);
    k_agg<<<aggGrid, 256>>>(hw, edges, rowstart, dinv, bb0, actA, bnsum + 0 * 256, N);
    k_bnfinal<<<1, CH>>>(bnsum + 0 * 256, gb0, betab0, bnsc + 0 * CH, bnsh + 0 * CH, (float)N);
    k_bn_gelu<<<2048, 256>>>(actA, bnsc + 0 * CH, bnsh + 0 * CH, n4);

    // ---- Layer 1: conv(actA, Wb1, bb1) -> actB (no BN) ----
    k_gemm<<<gemmGrid, 256>>>(actA, Wb1, dinv, hw, N);
    k_agg<<<aggGrid, 256>>>(hw, edges, rowstart, dinv, bb1, actB, nullptr, N);

    // ---- Layer 2: conv(actB, Wa0, ba0) -> BN1 -> gelu (in actA) ----
    k_gemm<<<gemmGrid, 256>>>(actB, Wa0, dinv, hw, N);
    k_agg<<<aggGrid, 256>>>(hw, edges, rowstart, dinv, ba0, actA, bnsum + 1 * 256, N);
    k_bnfinal<<<1, CH>>>(bnsum + 1 * 256, ga0, bea0, bnsc + 1 * CH, bnsh + 1 * CH, (float)N);
    k_bn_gelu<<<2048, 256>>>(actA, bnsc + 1 * CH, bnsh + 1 * CH, n4);

    // ---- Layer 3: conv(actA, Wa1, ba1) -> BN2 -> gelu (in actB) ----
    k_gemm<<<gemmGrid, 256>>>(actA, Wa1, dinv, hw, N);
    k_agg<<<aggGrid, 256>>>(hw, edges, rowstart, dinv, ba1, actB, bnsum + 2 * 256, N);
    k_bnfinal<<<1, CH>>>(bnsum + 2 * 256, ga1, bea1, bnsc + 2 * CH, bnsh + 2 * CH, (float)N);
    k_bn_gelu<<<2048, 256>>>(actB, bnsc + 2 * CH, bnsh + 2 * CH, n4);

    // ---- Layer 4: conv(actB, Wa2, ba2) -> actA (no activation) ----
    k_gemm<<<gemmGrid, 256>>>(actB, Wa2, dinv, hw, N);
    k_agg<<<aggGrid, 256>>>(hw, edges, rowstart, dinv, ba2, actA, nullptr, N);

    // ---- global mean pool ----
    k_pool<<<64, 256>>>(actA, batch, pool, pool + NGRAPHS * CH, N);

    // ---- MLP head ----
    k_head1<<<NGRAPHS, CH>>>(pool, pool + NGRAPHS * CH, Wh0, bh0, y1);
    k_head2<<<NGRAPHS, CH>>>(y1, Wh1, bh1, y2);
    k_head3<<<NGRAPHS, CH>>>(y2, Wh2, bh2, (float*)d_out);
}